// round 5
// baseline (speedup 1.0000x reference)
#include <cuda_runtime.h>
#include <cuda_bf16.h>

// TimeWarp, single fused kernel, fine-grained j-tiles.
// Block = (b, j-tile of TILE_J=64 time steps), covering ALL 128 freq rows.
//   Setup:  wy[64], per-chunk Y[16], x-resampled P-tile (<=8 rows x 128) in smem.
//   Stream: out[b,i,j] = lerp_y over smem P-tile; coalesced STG.128 streaming stores.
// B=32, F=128, T=8192, fp32.

#define NB 32
#define NF 128
#define NT 8192
#define TILE_J   64               // j's per block
#define TILE_C   (TILE_J / 4)     // 16 float4-chunks per block
#define MAX_ROWS 8                // y-span over 64 j's ~1.0 (+2 lerp +1) -> <=5; 8 is safe

__global__ __launch_bounds__(256, 8)
void timewarp_fused(const float* __restrict__ S,
                    const int*   __restrict__ psrc,
                    const int*   __restrict__ pdst,
                    float*       __restrict__ out)
{
    __shared__ float  sP[MAX_ROWS * NF];     // x-resampled rows [Ymin .. Ymin+nrows)
    __shared__ float4 sWy4[TILE_C];          // frac(y) per j, viewed as float4 per chunk
    __shared__ int    sYc[TILE_C];           // floor(y) at each chunk's first j

    const int t  = threadIdx.x;              // 256 threads
    const int jt = blockIdx.x;               // 0..127 j-tile
    const int b  = blockIdx.y;               // 0..31  batch
    const int j_base = jt * TILE_J;

    // ---------- Phase 1a: per-j tables (first 64 threads) ----------
    if (t < TILE_J) {
        const float s = (float)__ldg(psrc);
        const float d = (float)__ldg(pdst);
        const float rl = s / d;
        const float rr = ((float)NT - s) / ((float)NT - d);

        float tf  = (float)(j_base + t);
        float idx = (tf < d) ? (tf * rl) : fmaf(tf - d, rr, s);
        idx = fminf(fmaxf(idx, 0.0f), (float)(NT - 1));
        float y = idx * (1.0f / (float)(NT - 1)) * (float)(NF - 1);
        y = fminf(fmaxf(y, 0.0f), (float)(NF - 1));
        float yf = floorf(y);
        ((float*)sWy4)[t] = y - yf;
        if ((t & 3) == 0) sYc[t >> 2] = (int)yf;
    }
    __syncthreads();

    // ---------- Phase 1b: build P-tile (x-resample needed rows) ----------
    const int Ymin  = sYc[0];                        // y(j) monotone nondecreasing
    int nrows = sYc[TILE_C - 1] + 2 - Ymin + 1;      // cover Y..Y+2 of last chunk
    if (nrows > MAX_ROWS) nrows = MAX_ROWS;

    const float* Sb = S + (size_t)b * (size_t)(NF * NT);
    for (int v = t; v < nrows * NF; v += 256) {
        const int r  = v >> 7;
        const int i  = v & (NF - 1);
        const int rs = min(Ymin + r, NF - 1);        // border clamp / pad rows

        float x_pix = ((float)i / (float)(NF - 1)) * (float)(NT - 1);
        x_pix = fminf(fmaxf(x_pix, 0.0f), (float)(NT - 1));
        const float x0f = floorf(x_pix);
        const int   x0  = (int)x0f;
        const int   x1  = min(x0 + 1, NT - 1);
        const float wx  = x_pix - x0f;

        const float* row = Sb + (size_t)rs * NT;
        const float v0 = __ldg(row + x0);
        const float v1 = __ldg(row + x1);
        sP[v] = fmaf(wx, v1 - v0, v0);
    }
    __syncthreads();

    // ---------- Phase 2: stream all 128 freq rows ----------
    const int tx = t & (TILE_C - 1);                 // chunk within tile
    const int ty = t >> 4;                           // i-offset 0..15

    const float4 wy = sWy4[tx];
    const int    rel = sYc[tx] - Ymin;               // 0..nrows-3
    const float* pc  = sP + rel * NF;

    const bool s1 = wy.y < wy.x;
    const bool s2 = wy.z < wy.x;
    const bool s3 = wy.w < wy.x;

    float* obase = out + ((size_t)b * NF) * (size_t)NT + (size_t)(j_base + tx * 4);

#pragma unroll
    for (int ig = 0; ig < NF / 16; ig++) {           // 8 iterations
        const int i = ig * 16 + ty;

        const float pA = pc[i];
        const float pB = pc[NF + i];
        const float pC = pc[2 * NF + i];

        float o0 = fmaf(wy.x, pB - pA, pA);
        float l1 = s1 ? pB : pA, h1 = s1 ? pC : pB;
        float l2 = s2 ? pB : pA, h2 = s2 ? pC : pB;
        float l3 = s3 ? pB : pA, h3 = s3 ? pC : pB;
        float o1 = fmaf(wy.y, h1 - l1, l1);
        float o2 = fmaf(wy.z, h2 - l2, l2);
        float o3 = fmaf(wy.w, h3 - l3, l3);

        __stcs(reinterpret_cast<float4*>(obase + (size_t)i * NT),
               make_float4(o0, o1, o2, o3));
    }
}

extern "C" void kernel_launch(void* const* d_in, const int* in_sizes, int n_in,
                              void* d_out, int out_size)
{
    const float* S    = (const float*)d_in[0];
    const int*   psrc = (const int*)d_in[1];
    const int*   pdst = (const int*)d_in[2];
    float*       out  = (float*)d_out;

    dim3 grid(NT / TILE_J, NB);   // 128 x 32 = 4096 blocks
    timewarp_fused<<<grid, 256>>>(S, psrc, pdst, out);
}

// round 6
// speedup vs baseline: 1.1339x; 1.1339x over previous
#include <cuda_runtime.h>
#include <cuda_bf16.h>

// TimeWarp, single fused kernel.
// Block = (b, j-tile of 256, i-group of 32 freq rows)  -> grid 4096, balanced waves,
// while keeping 1KB contiguous stores per row (TILE_J=256).
//   Setup:  wy[256], per-chunk Y[64], x-resampled P-tile (<=12 rows x 32 i's) in smem.
//   Stream: out[b,i,j] = lerp_y over smem P-tile; coalesced STG.128 streaming stores.
// B=32, F=128, T=8192, fp32.

#define NB 32
#define NF 128
#define NT 8192
#define TILE_J   256              // j's per block
#define TILE_C   (TILE_J / 4)     // 64 float4-chunks per block
#define TILE_I   32               // freq rows per block
#define MAX_ROWS 12               // y-span over 256 j's <= ~4.1 (+2 lerp +1) -> <=8; 12 safe

__global__ __launch_bounds__(256, 8)
void timewarp_fused(const float* __restrict__ S,
                    const int*   __restrict__ psrc,
                    const int*   __restrict__ pdst,
                    float*       __restrict__ out)
{
    __shared__ float  sP[MAX_ROWS * TILE_I];   // x-resampled rows [Ymin..), i-slice only
    __shared__ float4 sWy4[TILE_C];            // frac(y) per j, float4 per chunk
    __shared__ int    sYc[TILE_C];             // floor(y) at each chunk's first j

    const int t  = threadIdx.x;                // 256 threads
    const int jt = blockIdx.x & 31;            // 0..31  j-tile
    const int ig = blockIdx.x >> 5;            // 0..3   i-group
    const int b  = blockIdx.y;                 // 0..31  batch
    const int j_base = jt * TILE_J;
    const int i_base = ig * TILE_I;

    // ---------- Phase 1a: per-j tables ----------
    {
        const float s = (float)__ldg(psrc);
        const float d = (float)__ldg(pdst);
        const float rl = s / d;
        const float rr = ((float)NT - s) / ((float)NT - d);

        float tf  = (float)(j_base + t);
        float idx = (tf < d) ? (tf * rl) : fmaf(tf - d, rr, s);
        idx = fminf(fmaxf(idx, 0.0f), (float)(NT - 1));
        float y = idx * (1.0f / (float)(NT - 1)) * (float)(NF - 1);
        y = fminf(fmaxf(y, 0.0f), (float)(NF - 1));
        float yf = floorf(y);
        ((float*)sWy4)[t] = y - yf;
        if ((t & 3) == 0) sYc[t >> 2] = (int)yf;
    }
    __syncthreads();

    // ---------- Phase 1b: build P-tile (x-resample needed rows, this i-slice) ----------
    const int Ymin  = sYc[0];                        // y(j) monotone nondecreasing
    int nrows = sYc[TILE_C - 1] + 2 - Ymin + 1;      // cover Y..Y+2 of last chunk
    if (nrows > MAX_ROWS) nrows = MAX_ROWS;

    const float* Sb = S + (size_t)b * (size_t)(NF * NT);
    for (int v = t; v < nrows * TILE_I; v += 256) {
        const int r  = v / TILE_I;
        const int il = v & (TILE_I - 1);
        const int i  = i_base + il;
        const int rs = min(Ymin + r, NF - 1);        // border clamp / pad rows

        float x_pix = ((float)i / (float)(NF - 1)) * (float)(NT - 1);
        x_pix = fminf(fmaxf(x_pix, 0.0f), (float)(NT - 1));
        const float x0f = floorf(x_pix);
        const int   x0  = (int)x0f;
        const int   x1  = min(x0 + 1, NT - 1);
        const float wx  = x_pix - x0f;

        const float* row = Sb + (size_t)rs * NT;
        const float v0 = __ldg(row + x0);
        const float v1 = __ldg(row + x1);
        sP[v] = fmaf(wx, v1 - v0, v0);
    }
    __syncthreads();

    // ---------- Phase 2: stream TILE_I freq rows x 256 j ----------
    const int tx = t & (TILE_C - 1);                 // chunk within tile (warp-contiguous)
    const int ty = t >> 6;                           // i-offset 0..3

    const float4 wy = sWy4[tx];
    const int    rel = sYc[tx] - Ymin;               // 0..nrows-3
    const float* pc  = sP + rel * TILE_I;

    const bool s1 = wy.y < wy.x;
    const bool s2 = wy.z < wy.x;
    const bool s3 = wy.w < wy.x;

    float* obase = out + ((size_t)b * NF + i_base) * (size_t)NT + (size_t)(j_base + tx * 4);

#pragma unroll
    for (int r = 0; r < TILE_I / 4; r++) {           // 8 iterations
        const int il = r * 4 + ty;

        const float pA = pc[il];
        const float pB = pc[TILE_I + il];
        const float pC = pc[2 * TILE_I + il];

        float o0 = fmaf(wy.x, pB - pA, pA);
        float l1 = s1 ? pB : pA, h1 = s1 ? pC : pB;
        float l2 = s2 ? pB : pA, h2 = s2 ? pC : pB;
        float l3 = s3 ? pB : pA, h3 = s3 ? pC : pB;
        float o1 = fmaf(wy.y, h1 - l1, l1);
        float o2 = fmaf(wy.z, h2 - l2, l2);
        float o3 = fmaf(wy.w, h3 - l3, l3);

        __stcs(reinterpret_cast<float4*>(obase + (size_t)il * NT),
               make_float4(o0, o1, o2, o3));
    }
}

extern "C" void kernel_launch(void* const* d_in, const int* in_sizes, int n_in,
                              void* d_out, int out_size)
{
    const float* S    = (const float*)d_in[0];
    const int*   psrc = (const int*)d_in[1];
    const int*   pdst = (const int*)d_in[2];
    float*       out  = (float*)d_out;

    dim3 grid((NT / TILE_J) * (NF / TILE_I), NB);    // (32*4) x 32 = 4096 blocks
    timewarp_fused<<<grid, 256>>>(S, psrc, pdst, out);
}